// round 14
// baseline (speedup 1.0000x reference)
#include <cuda_runtime.h>
#include <cuda_bf16.h>
#include <mma.h>
#include <math.h>
#include <stdint.h>

using namespace nvcuda;

#define N_NODES 50000
#define N_EDGES 800000
#define N_PRED  100000
#define D_IN    256
#define D_CAT   512   // q|k|v|skip concatenated, each 128

// ================= scratch (device globals; no allocation allowed) =================
__device__ __align__(16) float g_qs [(size_t)N_NODES * 128];   // q  (fp32 compact)
__device__ __align__(16) float g_sk [(size_t)N_NODES * 128];   // skip (fp32 compact)
__device__ __align__(16) __nv_bfloat16 g_kb[(size_t)N_NODES * 128];  // k (bf16 compact)
__device__ __align__(16) __nv_bfloat16 g_vb[(size_t)N_NODES * 128];  // v (bf16 compact)
__device__ __align__(16) float g_h2 [(size_t)N_NODES * 128];   // layer2 attn out (final)
__device__ __align__(16) __nv_bfloat16 g_xhi[(size_t)N_NODES * D_IN];
__device__ __align__(16) __nv_bfloat16 g_xlo[(size_t)N_NODES * D_IN];
__device__ __align__(16) __nv_bfloat16 g_hhi[(size_t)N_NODES * 128];
__device__ __align__(16) __nv_bfloat16 g_hlo[(size_t)N_NODES * 128];
__device__ __align__(16) __nv_bfloat16 g_Wt1h[D_CAT * D_IN];   // [512, 256] = W^T (K-major)
__device__ __align__(16) __nv_bfloat16 g_Wt1l[D_CAT * D_IN];
__device__ __align__(16) __nv_bfloat16 g_Wt2h[D_CAT * 128];
__device__ __align__(16) __nv_bfloat16 g_Wt2l[D_CAT * 128];
__device__ __align__(16) float g_brep1[16 * D_CAT];   // bias replicated over 16 rows
__device__ __align__(16) float g_brep2[16 * D_CAT];
__device__ int g_cnt[N_NODES];          // .bss zero at load; re-zeroed by scan_kernel
__device__ int g_off[N_NODES + 1];
__device__ int g_cur[N_NODES];
__device__ int g_csr_src[N_EDGES];
// degree-sorted node permutation (skew balancing for attention)
__device__ int g_dhist[64];             // .bss zero; re-zeroed by pscan_kernel
__device__ int g_dbase[64];
__device__ int g_perm[N_NODES];

// ================= cp.async helpers =================
__device__ __forceinline__ uint32_t smem_u32(const void* p) {
    uint32_t a;
    asm("{ .reg .u64 t; cvta.to.shared.u64 t, %1; cvt.u32.u64 %0, t; }" : "=r"(a) : "l"(p));
    return a;
}
#define CP_ASYNC16(dst, src) \
    asm volatile("cp.async.cg.shared.global [%0], [%1], 16;" :: "r"(dst), "l"(src))
#define CP_COMMIT() asm volatile("cp.async.commit_group;" ::: "memory")
#define CP_WAIT(n)  asm volatile("cp.async.wait_group %0;" :: "n"(n) : "memory")

// ================= split conversion: x -> hi/lo bf16 =================
__global__ void split_kernel(const float* __restrict__ src, __nv_bfloat16* __restrict__ hi,
                             __nv_bfloat16* __restrict__ lo, int n) {
    int i = blockIdx.x * blockDim.x + threadIdx.x;
    if (i < n) {
        float v = src[i];
        __nv_bfloat16 h = __float2bfloat16(v);
        hi[i] = h;
        lo[i] = __float2bfloat16(v - __bfloat162float(h));
    }
}

// ================= weight pack: Wt[n, k] = W_g[k, c] (transposed, split) ===========
__global__ void packW_kernel(const float* __restrict__ Wq, const float* __restrict__ Wk,
                             const float* __restrict__ Wv, const float* __restrict__ Ws,
                             const float* __restrict__ bq, const float* __restrict__ bk,
                             const float* __restrict__ bv, const float* __restrict__ bs,
                             __nv_bfloat16* __restrict__ Wth, __nv_bfloat16* __restrict__ Wtl,
                             float* __restrict__ brep, int K) {
    int idx = blockIdx.x * blockDim.x + threadIdx.x;
    int total = D_CAT * K;
    if (idx < total) {
        int n = idx / K, k = idx - n * K;
        int g = n >> 7, c = n & 127;
        const float* W = (g == 0) ? Wq : (g == 1) ? Wk : (g == 2) ? Wv : Ws;
        float v = W[k * 128 + c];
        __nv_bfloat16 h = __float2bfloat16(v);
        Wth[idx] = h;
        Wtl[idx] = __float2bfloat16(v - __bfloat162float(h));
    }
    if (idx < D_CAT) {
        int g = idx >> 7, c = idx & 127;
        const float* b = (g == 0) ? bq : (g == 1) ? bk : (g == 2) ? bv : bs;
        float bv2 = b[c];
#pragma unroll
        for (int r = 0; r < 16; r++) brep[r * D_CAT + idx] = bv2;
    }
}

// ================= CSR build (cnt==0 invariant; no zero kernel) =================
__global__ void count_kernel(const int* __restrict__ ei, int* __restrict__ cnt) {
    int e = blockIdx.x * blockDim.x + threadIdx.x;
    if (e < N_EDGES) atomicAdd(&cnt[ei[N_EDGES + e]], 1);
}
// single-block scan; re-zeroes cnt at the end (restores invariant for next launch)
__global__ void scan_kernel(int* __restrict__ cnt, int* __restrict__ off,
                            int* __restrict__ cur) {
    __shared__ int part[1024];
    int tid = threadIdx.x;
    const int CH = (N_NODES + 1023) / 1024;
    int base = tid * CH, s = 0;
    for (int i = 0; i < CH; i++) { int idx = base + i; if (idx < N_NODES) s += cnt[idx]; }
    part[tid] = s;
    __syncthreads();
    for (int d = 1; d < 1024; d <<= 1) {
        int v = (tid >= d) ? part[tid - d] : 0;
        __syncthreads();
        part[tid] += v;
        __syncthreads();
    }
    int run = (tid > 0) ? part[tid - 1] : 0;
    for (int i = 0; i < CH; i++) {
        int idx = base + i;
        if (idx < N_NODES) { off[idx] = run; cur[idx] = run; run += cnt[idx]; }
    }
    if (tid == 1023) off[N_NODES] = part[1023];
    for (int i = 0; i < CH; i++) {
        int idx = base + i;
        if (idx < N_NODES) cnt[idx] = 0;
    }
}
__global__ void scatter_kernel(const int* __restrict__ ei, int* __restrict__ cur,
                               int* __restrict__ csr_src) {
    int e = blockIdx.x * blockDim.x + threadIdx.x;
    if (e < N_EDGES) {
        int p = atomicAdd(&cur[ei[N_EDGES + e]], 1);
        csr_src[p] = ei[e];
    }
}

// ================= degree-sorted permutation (attention load balance) =============
__global__ void phist_kernel(const int* __restrict__ off, int* __restrict__ dhist) {
    int i = blockIdx.x * blockDim.x + threadIdx.x;
    if (i < N_NODES) {
        int d = off[i + 1] - off[i];
        if (d > 63) d = 63;
        atomicAdd(&dhist[d], 1);
    }
}
// serial 64-bin exclusive scan, DESCENDING degree (long nodes first);
// restores dhist==0 invariant after use.
__global__ void pscan_kernel(int* __restrict__ dhist, int* __restrict__ dbase) {
    if (threadIdx.x == 0) {
        int run = 0;
        for (int b = 63; b >= 0; b--) { dbase[b] = run; run += dhist[b]; }
        for (int b = 0; b < 64; b++) dhist[b] = 0;
    }
}
__global__ void pscatter_kernel(const int* __restrict__ off, int* __restrict__ dbase,
                                int* __restrict__ perm) {
    int i = blockIdx.x * blockDim.x + threadIdx.x;
    if (i < N_NODES) {
        int d = off[i + 1] - off[i];
        if (d > 63) d = 63;
        int pos = atomicAdd(&dbase[d], 1);
        perm[pos] = i;
    }
}

// ================= HMMA (wmma) GEMM with sectioned epilogue ========================
// CTA tile 128x128, 8 warps (4x2), warp tile 32x64, K-chunks 32, double-buffered.
// blockIdx.x = output section: 0=q(f32), 1=k(bf16), 2=v(bf16), 3=skip(f32).
#define TM 128
#define TN 128
#define TKC 32
#define LDA 40                    // smem k-stride (bf16); row = 80B (16B-aligned)
#define TILE_B (TM * LDA * 2)     // 10240 bytes per (part) tile
#define STAGE_B (4 * TILE_B)      // Ahi|Alo|Bhi|Blo = 40960 bytes
#define GEMM_SMEM (2 * STAGE_B)   // 81920 -> 2 CTAs/SM

__global__ void __launch_bounds__(256, 2) gemm_tc_kernel(
    const __nv_bfloat16* __restrict__ Ahi, const __nv_bfloat16* __restrict__ Alo,
    const __nv_bfloat16* __restrict__ Wth, const __nv_bfloat16* __restrict__ Wtl,
    const float* __restrict__ brep,
    float* __restrict__ Oq, __nv_bfloat16* __restrict__ Ok,
    __nv_bfloat16* __restrict__ Ov, float* __restrict__ Os, int M, int K) {
    extern __shared__ char smem[];
    int tid = threadIdx.x;
    int wid = tid >> 5;
    int warp_m = wid & 3;
    int warp_n = wid >> 2;
    int row0 = blockIdx.y * TM;
    int col0 = blockIdx.x * TN;
    int nchunks = K / TKC;

    uint32_t smem_base = smem_u32(smem);

    auto load_chunk = [&](int ch, int s) {
        char* st = smem + s * STAGE_B;
        int k0 = ch * TKC;
        for (int i = tid; i < 512; i += 256) {
            int r = i >> 2;
            int kc = (i & 3) * 8;
            int grow = row0 + r;
            uint32_t dh = smem_base + s * STAGE_B + 0 * TILE_B + (r * LDA + kc) * 2;
            uint32_t dl = dh + TILE_B;
            if (grow < M) {
                CP_ASYNC16(dh, Ahi + (size_t)grow * K + k0 + kc);
                CP_ASYNC16(dl, Alo + (size_t)grow * K + k0 + kc);
            } else {
                *(uint4*)(st + 0 * TILE_B + (r * LDA + kc) * 2) = make_uint4(0, 0, 0, 0);
                *(uint4*)(st + 1 * TILE_B + (r * LDA + kc) * 2) = make_uint4(0, 0, 0, 0);
            }
        }
        for (int i = tid; i < 512; i += 256) {
            int n = i >> 2;
            int kc = (i & 3) * 8;
            int gn = col0 + n;
            uint32_t dh = smem_base + s * STAGE_B + 2 * TILE_B + (n * LDA + kc) * 2;
            uint32_t dl = dh + TILE_B;
            CP_ASYNC16(dh, Wth + (size_t)gn * K + k0 + kc);
            CP_ASYNC16(dl, Wtl + (size_t)gn * K + k0 + kc);
        }
        CP_COMMIT();
    };

    wmma::fragment<wmma::accumulator, 16, 16, 16, float> acc[2][4];
#pragma unroll
    for (int mi = 0; mi < 2; mi++)
#pragma unroll
        for (int ni = 0; ni < 4; ni++)
            wmma::load_matrix_sync(acc[mi][ni], brep + col0 + warp_n * 64 + ni * 16,
                                   D_CAT, wmma::mem_row_major);

    load_chunk(0, 0);

    for (int ch = 0; ch < nchunks; ch++) {
        int s = ch & 1;
        CP_WAIT(0);
        __syncthreads();
        if (ch + 1 < nchunks)
            load_chunk(ch + 1, s ^ 1);

        const __nv_bfloat16* sAhi = (const __nv_bfloat16*)(smem + s * STAGE_B);
        const __nv_bfloat16* sBhi = (const __nv_bfloat16*)(smem + s * STAGE_B + 2 * TILE_B);

#pragma unroll
        for (int ks = 0; ks < TKC / 16; ks++) {
            wmma::fragment<wmma::matrix_a, 16, 16, 16, __nv_bfloat16, wmma::row_major> ah[2], al[2];
#pragma unroll
            for (int mi = 0; mi < 2; mi++) {
                const __nv_bfloat16* pa = sAhi + (warp_m * 32 + mi * 16) * LDA + ks * 16;
                wmma::load_matrix_sync(ah[mi], pa, LDA);
                wmma::load_matrix_sync(al[mi], pa + (TILE_B / 2), LDA);
            }
#pragma unroll
            for (int ni = 0; ni < 4; ni++) {
                wmma::fragment<wmma::matrix_b, 16, 16, 16, __nv_bfloat16, wmma::col_major> bh, bl;
                const __nv_bfloat16* pb = sBhi + (warp_n * 64 + ni * 16) * LDA + ks * 16;
                wmma::load_matrix_sync(bh, pb, LDA);
                wmma::load_matrix_sync(bl, pb + (TILE_B / 2), LDA);
#pragma unroll
                for (int mi = 0; mi < 2; mi++) {
                    wmma::mma_sync(acc[mi][ni], ah[mi], bh, acc[mi][ni]);
                    wmma::mma_sync(acc[mi][ni], ah[mi], bl, acc[mi][ni]);
                    wmma::mma_sync(acc[mi][ni], al[mi], bh, acc[mi][ni]);
                }
            }
        }
    }
    __syncthreads();

    // ---- sectioned epilogue ----
    int sec = blockIdx.x;
    float* warpbuf = (float*)(smem) + wid * 256;
    int lane = tid & 31;

    if (sec == 0 || sec == 3) {
        float* dst = (sec == 0) ? Oq : Os;
#pragma unroll
        for (int mi = 0; mi < 2; mi++) {
            int rbase = row0 + warp_m * 32 + mi * 16;
            bool full = (rbase + 16 <= M);
#pragma unroll
            for (int ni = 0; ni < 4; ni++) {
                int cl = warp_n * 64 + ni * 16;
                if (full) {
                    wmma::store_matrix_sync(dst + (size_t)rbase * 128 + cl, acc[mi][ni],
                                            128, wmma::mem_row_major);
                } else {
                    wmma::store_matrix_sync(warpbuf, acc[mi][ni], 16, wmma::mem_row_major);
                    __syncwarp();
                    int r = lane >> 1;
                    int c8 = (lane & 1) * 8;
                    int gr = rbase + r;
                    if (gr < M) {
                        float4 v0 = *(float4*)(warpbuf + r * 16 + c8);
                        float4 v1 = *(float4*)(warpbuf + r * 16 + c8 + 4);
                        *(float4*)(dst + (size_t)gr * 128 + cl + c8) = v0;
                        *(float4*)(dst + (size_t)gr * 128 + cl + c8 + 4) = v1;
                    }
                    __syncwarp();
                }
            }
        }
    } else {
        __nv_bfloat16* dst = (sec == 1) ? Ok : Ov;
#pragma unroll
        for (int mi = 0; mi < 2; mi++) {
            int rbase = row0 + warp_m * 32 + mi * 16;
#pragma unroll
            for (int ni = 0; ni < 4; ni++) {
                int cl = warp_n * 64 + ni * 16;
                wmma::store_matrix_sync(warpbuf, acc[mi][ni], 16, wmma::mem_row_major);
                __syncwarp();
                int r = lane >> 1;
                int c8 = (lane & 1) * 8;
                int gr = rbase + r;
                if (gr < M) {
                    float4 v0 = *(float4*)(warpbuf + r * 16 + c8);
                    float4 v1 = *(float4*)(warpbuf + r * 16 + c8 + 4);
                    __nv_bfloat162 b0 = __float22bfloat162_rn(make_float2(v0.x, v0.y));
                    __nv_bfloat162 b1 = __float22bfloat162_rn(make_float2(v0.z, v0.w));
                    __nv_bfloat162 b2 = __float22bfloat162_rn(make_float2(v1.x, v1.y));
                    __nv_bfloat162 b3 = __float22bfloat162_rn(make_float2(v1.z, v1.w));
                    uint4 pk;
                    pk.x = *(uint32_t*)&b0; pk.y = *(uint32_t*)&b1;
                    pk.z = *(uint32_t*)&b2; pk.w = *(uint32_t*)&b3;
                    *(uint4*)(dst + (size_t)gr * 128 + cl + c8) = pk;
                }
                __syncwarp();
            }
        }
    }
}

// ================= fused attention: degree-sorted warp->node mapping ================
// k,v bf16 [N,128] (25.6MB, L2-resident); q,skip fp32 [N,128]; warp handles perm[w].
__global__ void __launch_bounds__(256) attn_kernel(
    const float* __restrict__ qs, const __nv_bfloat16* __restrict__ kb,
    const __nv_bfloat16* __restrict__ vb, const float* __restrict__ sk,
    const int* __restrict__ off, const int* __restrict__ csr_src,
    const int* __restrict__ perm,
    float* __restrict__ out_f32, __nv_bfloat16* __restrict__ out_hi,
    __nv_bfloat16* __restrict__ out_lo, int mode) {
    int w = (blockIdx.x * blockDim.x + threadIdx.x) >> 5;
    int lane = threadIdx.x & 31;
    if (w >= N_NODES) return;
    int node = perm[w];
    const float scale = 0.0883883476483184f;   // 1/sqrt(128)

    float4 q = *(const float4*)(qs + (size_t)node * 128 + lane * 4);
    int e0 = off[node], e1 = off[node + 1];

    float ax = 0.f, ay = 0.f, az = 0.f, aw = 0.f, den = 0.f;
    int e = e0;
    for (; e + 2 <= e1; e += 2) {
        int s0 = csr_src[e];
        int s1 = csr_src[e + 1];
        uint2 kw0 = *(const uint2*)(kb + (size_t)s0 * 128 + lane * 4);
        uint2 kw1 = *(const uint2*)(kb + (size_t)s1 * 128 + lane * 4);
        uint2 vw0 = *(const uint2*)(vb + (size_t)s0 * 128 + lane * 4);
        uint2 vw1 = *(const uint2*)(vb + (size_t)s1 * 128 + lane * 4);
        float2 k0a = __bfloat1622float2(*(__nv_bfloat162*)&kw0.x);
        float2 k0b = __bfloat1622float2(*(__nv_bfloat162*)&kw0.y);
        float2 k1a = __bfloat1622float2(*(__nv_bfloat162*)&kw1.x);
        float2 k1b = __bfloat1622float2(*(__nv_bfloat162*)&kw1.y);
        float p0 = q.x * k0a.x + q.y * k0a.y + q.z * k0b.x + q.w * k0b.y;
        float p1 = q.x * k1a.x + q.y * k1a.y + q.z * k1b.x + q.w * k1b.y;
        p0 += __shfl_xor_sync(0xFFFFFFFFu, p0, 16);
        p1 += __shfl_xor_sync(0xFFFFFFFFu, p1, 16);
        p0 += __shfl_xor_sync(0xFFFFFFFFu, p0, 8);
        p1 += __shfl_xor_sync(0xFFFFFFFFu, p1, 8);
        p0 += __shfl_xor_sync(0xFFFFFFFFu, p0, 4);
        p1 += __shfl_xor_sync(0xFFFFFFFFu, p1, 4);
        p0 += __shfl_xor_sync(0xFFFFFFFFu, p0, 2);
        p1 += __shfl_xor_sync(0xFFFFFFFFu, p1, 2);
        p0 += __shfl_xor_sync(0xFFFFFFFFu, p0, 1);
        p1 += __shfl_xor_sync(0xFFFFFFFFu, p1, 1);
        float ex0 = __expf(p0 * scale);
        float ex1 = __expf(p1 * scale);
        float2 v0a = __bfloat1622float2(*(__nv_bfloat162*)&vw0.x);
        float2 v0b = __bfloat1622float2(*(__nv_bfloat162*)&vw0.y);
        float2 v1a = __bfloat1622float2(*(__nv_bfloat162*)&vw1.x);
        float2 v1b = __bfloat1622float2(*(__nv_bfloat162*)&vw1.y);
        ax += ex0 * v0a.x + ex1 * v1a.x;
        ay += ex0 * v0a.y + ex1 * v1a.y;
        az += ex0 * v0b.x + ex1 * v1b.x;
        aw += ex0 * v0b.y + ex1 * v1b.y;
        den += ex0 + ex1;
    }
    if (e < e1) {
        int s0 = csr_src[e];
        uint2 kw0 = *(const uint2*)(kb + (size_t)s0 * 128 + lane * 4);
        uint2 vw0 = *(const uint2*)(vb + (size_t)s0 * 128 + lane * 4);
        float2 k0a = __bfloat1622float2(*(__nv_bfloat162*)&kw0.x);
        float2 k0b = __bfloat1622float2(*(__nv_bfloat162*)&kw0.y);
        float p0 = q.x * k0a.x + q.y * k0a.y + q.z * k0b.x + q.w * k0b.y;
        p0 += __shfl_xor_sync(0xFFFFFFFFu, p0, 16);
        p0 += __shfl_xor_sync(0xFFFFFFFFu, p0, 8);
        p0 += __shfl_xor_sync(0xFFFFFFFFu, p0, 4);
        p0 += __shfl_xor_sync(0xFFFFFFFFu, p0, 2);
        p0 += __shfl_xor_sync(0xFFFFFFFFu, p0, 1);
        float ex0 = __expf(p0 * scale);
        float2 v0a = __bfloat1622float2(*(__nv_bfloat162*)&vw0.x);
        float2 v0b = __bfloat1622float2(*(__nv_bfloat162*)&vw0.y);
        ax += ex0 * v0a.x; ay += ex0 * v0a.y; az += ex0 * v0b.x; aw += ex0 * v0b.y;
        den += ex0;
    }
    float inv = (e1 > e0) ? 1.0f / den : 0.0f;
    float4 skv = *(const float4*)(sk + (size_t)node * 128 + lane * 4);
    float4 r;
    r.x = ax * inv + skv.x;
    r.y = ay * inv + skv.y;
    r.z = az * inv + skv.z;
    r.w = aw * inv + skv.w;
    if (mode == 1) {
        r.x = fmaxf(r.x, 0.f); r.y = fmaxf(r.y, 0.f);
        r.z = fmaxf(r.z, 0.f); r.w = fmaxf(r.w, 0.f);
        __nv_bfloat162 h0 = __float22bfloat162_rn(make_float2(r.x, r.y));
        __nv_bfloat162 h1 = __float22bfloat162_rn(make_float2(r.z, r.w));
        float2 hr0 = __bfloat1622float2(h0), hr1 = __bfloat1622float2(h1);
        __nv_bfloat162 l0 = __float22bfloat162_rn(make_float2(r.x - hr0.x, r.y - hr0.y));
        __nv_bfloat162 l1 = __float22bfloat162_rn(make_float2(r.z - hr1.x, r.w - hr1.y));
        size_t base = (size_t)node * 128 + lane * 4;
        *(__nv_bfloat162*)(out_hi + base)     = h0;
        *(__nv_bfloat162*)(out_hi + base + 2) = h1;
        *(__nv_bfloat162*)(out_lo + base)     = l0;
        *(__nv_bfloat162*)(out_lo + base + 2) = l1;
    } else {
        *(float4*)(out_f32 + (size_t)node * 128 + lane * 4) = r;
    }
}

// ================= edge scorer: (h[a]*h[b]) @ Wl + bl =================
__global__ void __launch_bounds__(256) score_kernel(
    const float* __restrict__ h, const int* __restrict__ pos,
    const int* __restrict__ neg, const float* __restrict__ Wl,
    const float* __restrict__ bl, float* __restrict__ out) {
    int warp = (blockIdx.x * blockDim.x + threadIdx.x) >> 5;
    int lane = threadIdx.x & 31;
    if (warp >= 2 * N_PRED) return;
    int a, b;
    if (warp < N_PRED) { a = pos[warp]; b = pos[N_PRED + warp]; }
    else { int i = warp - N_PRED; a = neg[i]; b = neg[N_PRED + i]; }
    float4 ha = *(const float4*)(h + (size_t)a * 128 + lane * 4);
    float4 hb = *(const float4*)(h + (size_t)b * 128 + lane * 4);
    float4 w  = *(const float4*)(Wl + lane * 4);
    float p = ha.x * hb.x * w.x + ha.y * hb.y * w.y + ha.z * hb.z * w.z + ha.w * hb.w * w.w;
    p += __shfl_xor_sync(0xFFFFFFFFu, p, 16);
    p += __shfl_xor_sync(0xFFFFFFFFu, p, 8);
    p += __shfl_xor_sync(0xFFFFFFFFu, p, 4);
    p += __shfl_xor_sync(0xFFFFFFFFu, p, 2);
    p += __shfl_xor_sync(0xFFFFFFFFu, p, 1);
    if (lane == 0) out[warp] = p + bl[0];
}

// ================= launch =================
extern "C" void kernel_launch(void* const* d_in, const int* in_sizes, int n_in,
                              void* d_out, int out_size) {
    const float* x   = (const float*)d_in[0];
    const int*   ei  = (const int*)d_in[1];    // int32 (JAX x64 disabled)
    const int*   pos = (const int*)d_in[2];
    const int*   neg = (const int*)d_in[3];
    const float *Wq1 = (const float*)d_in[4],  *bq1 = (const float*)d_in[5];
    const float *Wk1 = (const float*)d_in[6],  *bk1 = (const float*)d_in[7];
    const float *Wv1 = (const float*)d_in[8],  *bv1 = (const float*)d_in[9];
    const float *Ws1 = (const float*)d_in[10], *bs1 = (const float*)d_in[11];
    const float *Wq2 = (const float*)d_in[12], *bq2 = (const float*)d_in[13];
    const float *Wk2 = (const float*)d_in[14], *bk2 = (const float*)d_in[15];
    const float *Wv2 = (const float*)d_in[16], *bv2 = (const float*)d_in[17];
    const float *Ws2 = (const float*)d_in[18], *bs2 = (const float*)d_in[19];
    const float *Wl  = (const float*)d_in[20], *bl  = (const float*)d_in[21];
    float* out = (float*)d_out;

    void *p;
    cudaGetSymbolAddress(&p, g_qs);    float* qs = (float*)p;
    cudaGetSymbolAddress(&p, g_sk);    float* sk = (float*)p;
    cudaGetSymbolAddress(&p, g_kb);    __nv_bfloat16* kb = (__nv_bfloat16*)p;
    cudaGetSymbolAddress(&p, g_vb);    __nv_bfloat16* vb = (__nv_bfloat16*)p;
    cudaGetSymbolAddress(&p, g_h2);    float* h2   = (float*)p;
    cudaGetSymbolAddress(&p, g_xhi);   __nv_bfloat16* xhi = (__nv_bfloat16*)p;
    cudaGetSymbolAddress(&p, g_xlo);   __nv_bfloat16* xlo = (__nv_bfloat16*)p;
    cudaGetSymbolAddress(&p, g_hhi);   __nv_bfloat16* hhi = (__nv_bfloat16*)p;
    cudaGetSymbolAddress(&p, g_hlo);   __nv_bfloat16* hlo = (__nv_bfloat16*)p;
    cudaGetSymbolAddress(&p, g_Wt1h);  __nv_bfloat16* Wt1h = (__nv_bfloat16*)p;
    cudaGetSymbolAddress(&p, g_Wt1l);  __nv_bfloat16* Wt1l = (__nv_bfloat16*)p;
    cudaGetSymbolAddress(&p, g_Wt2h);  __nv_bfloat16* Wt2h = (__nv_bfloat16*)p;
    cudaGetSymbolAddress(&p, g_Wt2l);  __nv_bfloat16* Wt2l = (__nv_bfloat16*)p;
    cudaGetSymbolAddress(&p, g_brep1); float* brep1 = (float*)p;
    cudaGetSymbolAddress(&p, g_brep2); float* brep2 = (float*)p;
    cudaGetSymbolAddress(&p, g_cnt);   int* cnt = (int*)p;
    cudaGetSymbolAddress(&p, g_off);   int* off = (int*)p;
    cudaGetSymbolAddress(&p, g_cur);   int* cur = (int*)p;
    cudaGetSymbolAddress(&p, g_csr_src); int* csr = (int*)p;
    cudaGetSymbolAddress(&p, g_dhist); int* dhist = (int*)p;
    cudaGetSymbolAddress(&p, g_dbase); int* dbase = (int*)p;
    cudaGetSymbolAddress(&p, g_perm);  int* perm  = (int*)p;

    cudaFuncSetAttribute(gemm_tc_kernel, cudaFuncAttributeMaxDynamicSharedMemorySize, GEMM_SMEM);

    dim3 ggrid(D_CAT / TN, (N_NODES + TM - 1) / TM);

    // prep (launches 0-2)
    split_kernel<<<(N_NODES * D_IN + 255) / 256, 256>>>(x, xhi, xlo, N_NODES * D_IN);
    packW_kernel<<<(D_CAT * D_IN + 255) / 256, 256>>>(Wq1, Wk1, Wv1, Ws1, bq1, bk1, bv1, bs1,
                                                      Wt1h, Wt1l, brep1, D_IN);
    packW_kernel<<<(D_CAT * 128 + 255) / 256, 256>>>(Wq2, Wk2, Wv2, Ws2, bq2, bk2, bv2, bs2,
                                                     Wt2h, Wt2l, brep2, 128);

    // GEMM layer 1 (launch index 3 — the one ncu profiles)
    gemm_tc_kernel<<<ggrid, 256, GEMM_SMEM>>>(xhi, xlo, Wt1h, Wt1l, brep1,
                                              qs, kb, vb, sk, N_NODES, D_IN);

    // CSR by dst (sequential; cnt==0 invariant)
    count_kernel<<<(N_EDGES + 255) / 256, 256>>>(ei, cnt);
    scan_kernel<<<1, 1024>>>(cnt, off, cur);
    scatter_kernel<<<(N_EDGES + 255) / 256, 256>>>(ei, cur, csr);

    // degree-sorted permutation (dhist==0 invariant)
    phist_kernel<<<(N_NODES + 255) / 256, 256>>>(off, dhist);
    pscan_kernel<<<1, 32>>>(dhist, dbase);
    pscatter_kernel<<<(N_NODES + 255) / 256, 256>>>(off, dbase, perm);

    // layer 1 attention
    attn_kernel<<<(N_NODES * 32 + 255) / 256, 256>>>(qs, kb, vb, sk, off, csr, perm,
                                                     nullptr, hhi, hlo, 1);

    // layer 2
    gemm_tc_kernel<<<ggrid, 256, GEMM_SMEM>>>(hhi, hlo, Wt2h, Wt2l, brep2,
                                              qs, kb, vb, sk, N_NODES, 128);
    attn_kernel<<<(N_NODES * 32 + 255) / 256, 256>>>(qs, kb, vb, sk, off, csr, perm,
                                                     h2, nullptr, nullptr, 0);

    // scorer
    score_kernel<<<(2 * N_PRED * 32 + 255) / 256, 256>>>(h2, pos, neg, Wl, bl, out);
}

// round 15
// speedup vs baseline: 1.0893x; 1.0893x over previous
#include <cuda_runtime.h>
#include <cuda_bf16.h>
#include <mma.h>
#include <math.h>
#include <stdint.h>

using namespace nvcuda;

#define N_NODES 50000
#define N_EDGES 800000
#define N_PRED  100000
#define D_IN    256
#define D_CAT   512   // q|k|v|skip concatenated, each 128

// ================= scratch (device globals; no allocation allowed) =================
__device__ __align__(16) float g_qs [(size_t)N_NODES * 128];   // q  (fp32 compact)
__device__ __align__(16) float g_sk [(size_t)N_NODES * 128];   // skip (fp32 compact)
__device__ __align__(16) __nv_bfloat16 g_kb[(size_t)N_NODES * 128];  // k (bf16 compact)
__device__ __align__(16) __nv_bfloat16 g_vb[(size_t)N_NODES * 128];  // v (bf16 compact)
__device__ __align__(16) float g_h2 [(size_t)N_NODES * 128];   // layer2 attn out (final)
__device__ __align__(16) __nv_bfloat16 g_xhi[(size_t)N_NODES * D_IN];
__device__ __align__(16) __nv_bfloat16 g_xlo[(size_t)N_NODES * D_IN];
__device__ __align__(16) __nv_bfloat16 g_hhi[(size_t)N_NODES * 128];
__device__ __align__(16) __nv_bfloat16 g_hlo[(size_t)N_NODES * 128];
__device__ __align__(16) __nv_bfloat16 g_Wt1h[D_CAT * D_IN];   // [512, 256] = W^T (K-major)
__device__ __align__(16) __nv_bfloat16 g_Wt1l[D_CAT * D_IN];
__device__ __align__(16) __nv_bfloat16 g_Wt2h[D_CAT * 128];
__device__ __align__(16) __nv_bfloat16 g_Wt2l[D_CAT * 128];
__device__ __align__(16) float g_brep1[16 * D_CAT];   // bias replicated over 16 rows
__device__ __align__(16) float g_brep2[16 * D_CAT];
__device__ int g_cnt[N_NODES];
__device__ int g_off[N_NODES + 1];
__device__ int g_cur[N_NODES];
__device__ int g_csr_src[N_EDGES];

// ================= cp.async helpers =================
__device__ __forceinline__ uint32_t smem_u32(const void* p) {
    uint32_t a;
    asm("{ .reg .u64 t; cvta.to.shared.u64 t, %1; cvt.u32.u64 %0, t; }" : "=r"(a) : "l"(p));
    return a;
}
#define CP_ASYNC16(dst, src) \
    asm volatile("cp.async.cg.shared.global [%0], [%1], 16;" :: "r"(dst), "l"(src))
#define CP_COMMIT() asm volatile("cp.async.commit_group;" ::: "memory")
#define CP_WAIT(n)  asm volatile("cp.async.wait_group %0;" :: "n"(n) : "memory")

// ================= split conversion: x -> hi/lo bf16 =================
__global__ void split_kernel(const float* __restrict__ src, __nv_bfloat16* __restrict__ hi,
                             __nv_bfloat16* __restrict__ lo, int n) {
    int i = blockIdx.x * blockDim.x + threadIdx.x;
    if (i < n) {
        float v = src[i];
        __nv_bfloat16 h = __float2bfloat16(v);
        hi[i] = h;
        lo[i] = __float2bfloat16(v - __bfloat162float(h));
    }
}

// ================= weight pack: Wt[n, k] = W_g[k, c] (transposed, split) ===========
__global__ void packW_kernel(const float* __restrict__ Wq, const float* __restrict__ Wk,
                             const float* __restrict__ Wv, const float* __restrict__ Ws,
                             const float* __restrict__ bq, const float* __restrict__ bk,
                             const float* __restrict__ bv, const float* __restrict__ bs,
                             __nv_bfloat16* __restrict__ Wth, __nv_bfloat16* __restrict__ Wtl,
                             float* __restrict__ brep, int K) {
    int idx = blockIdx.x * blockDim.x + threadIdx.x;
    int total = D_CAT * K;
    if (idx < total) {
        int n = idx / K, k = idx - n * K;
        int g = n >> 7, c = n & 127;
        const float* W = (g == 0) ? Wq : (g == 1) ? Wk : (g == 2) ? Wv : Ws;
        float v = W[k * 128 + c];
        __nv_bfloat16 h = __float2bfloat16(v);
        Wth[idx] = h;
        Wtl[idx] = __float2bfloat16(v - __bfloat162float(h));
    }
    if (idx < D_CAT) {
        int g = idx >> 7, c = idx & 127;
        const float* b = (g == 0) ? bq : (g == 1) ? bk : (g == 2) ? bv : bs;
        float bv2 = b[c];
#pragma unroll
        for (int r = 0; r < 16; r++) brep[r * D_CAT + idx] = bv2;
    }
}

// ================= CSR build =================
__global__ void zero_cnt_kernel(int* __restrict__ cnt) {
    int i = blockIdx.x * blockDim.x + threadIdx.x;
    if (i < N_NODES) cnt[i] = 0;
}
__global__ void count_kernel(const int* __restrict__ ei, int* __restrict__ cnt) {
    int e = blockIdx.x * blockDim.x + threadIdx.x;
    if (e < N_EDGES) atomicAdd(&cnt[ei[N_EDGES + e]], 1);
}
__global__ void scan_kernel(const int* __restrict__ cnt, int* __restrict__ off,
                            int* __restrict__ cur) {
    __shared__ int part[1024];
    int tid = threadIdx.x;
    const int CH = (N_NODES + 1023) / 1024;
    int base = tid * CH, s = 0;
    for (int i = 0; i < CH; i++) { int idx = base + i; if (idx < N_NODES) s += cnt[idx]; }
    part[tid] = s;
    __syncthreads();
    for (int d = 1; d < 1024; d <<= 1) {
        int v = (tid >= d) ? part[tid - d] : 0;
        __syncthreads();
        part[tid] += v;
        __syncthreads();
    }
    int run = (tid > 0) ? part[tid - 1] : 0;
    for (int i = 0; i < CH; i++) {
        int idx = base + i;
        if (idx < N_NODES) { off[idx] = run; cur[idx] = run; run += cnt[idx]; }
    }
    if (tid == 1023) off[N_NODES] = part[1023];
}
__global__ void scatter_kernel(const int* __restrict__ ei, int* __restrict__ cur,
                               int* __restrict__ csr_src) {
    int e = blockIdx.x * blockDim.x + threadIdx.x;
    if (e < N_EDGES) {
        int p = atomicAdd(&cur[ei[N_EDGES + e]], 1);
        csr_src[p] = ei[e];
    }
}

// ================= HMMA (wmma) GEMM with sectioned epilogue ========================
// CTA tile 128x128, 8 warps (4x2), warp tile 32x64, K-chunks 32, double-buffered.
// blockIdx.x = output section: 0=q(f32), 1=k(bf16), 2=v(bf16), 3=skip(f32);
// each section written to its own compact [N,128] array (k/v bf16 => attention
// working set 25.6MB, fully L2-resident).
#define TM 128
#define TN 128
#define TKC 32
#define LDA 40                    // smem k-stride (bf16); row = 80B (16B-aligned)
#define TILE_B (TM * LDA * 2)     // 10240 bytes per (part) tile
#define STAGE_B (4 * TILE_B)      // Ahi|Alo|Bhi|Blo = 40960 bytes
#define GEMM_SMEM (2 * STAGE_B)   // 81920 -> 2 CTAs/SM

__global__ void __launch_bounds__(256, 2) gemm_tc_kernel(
    const __nv_bfloat16* __restrict__ Ahi, const __nv_bfloat16* __restrict__ Alo,
    const __nv_bfloat16* __restrict__ Wth, const __nv_bfloat16* __restrict__ Wtl,
    const float* __restrict__ brep,
    float* __restrict__ Oq, __nv_bfloat16* __restrict__ Ok,
    __nv_bfloat16* __restrict__ Ov, float* __restrict__ Os, int M, int K) {
    extern __shared__ char smem[];
    int tid = threadIdx.x;
    int wid = tid >> 5;
    int warp_m = wid & 3;      // 4 warps over M (32 rows each)
    int warp_n = wid >> 2;     // 2 warps over N (64 cols each)
    int row0 = blockIdx.y * TM;
    int col0 = blockIdx.x * TN;    // section base: 0,128,256,384
    int nchunks = K / TKC;

    uint32_t smem_base = smem_u32(smem);

    auto load_chunk = [&](int ch, int s) {
        char* st = smem + s * STAGE_B;
        int k0 = ch * TKC;
        for (int i = tid; i < 512; i += 256) {
            int r = i >> 2;
            int kc = (i & 3) * 8;
            int grow = row0 + r;
            uint32_t dh = smem_base + s * STAGE_B + 0 * TILE_B + (r * LDA + kc) * 2;
            uint32_t dl = dh + TILE_B;
            if (grow < M) {
                CP_ASYNC16(dh, Ahi + (size_t)grow * K + k0 + kc);
                CP_ASYNC16(dl, Alo + (size_t)grow * K + k0 + kc);
            } else {
                *(uint4*)(st + 0 * TILE_B + (r * LDA + kc) * 2) = make_uint4(0, 0, 0, 0);
                *(uint4*)(st + 1 * TILE_B + (r * LDA + kc) * 2) = make_uint4(0, 0, 0, 0);
            }
        }
        for (int i = tid; i < 512; i += 256) {
            int n = i >> 2;
            int kc = (i & 3) * 8;
            int gn = col0 + n;
            uint32_t dh = smem_base + s * STAGE_B + 2 * TILE_B + (n * LDA + kc) * 2;
            uint32_t dl = dh + TILE_B;
            CP_ASYNC16(dh, Wth + (size_t)gn * K + k0 + kc);
            CP_ASYNC16(dl, Wtl + (size_t)gn * K + k0 + kc);
        }
        CP_COMMIT();
    };

    // accumulators init = bias (all 16 rows of brep identical)
    wmma::fragment<wmma::accumulator, 16, 16, 16, float> acc[2][4];
#pragma unroll
    for (int mi = 0; mi < 2; mi++)
#pragma unroll
        for (int ni = 0; ni < 4; ni++)
            wmma::load_matrix_sync(acc[mi][ni], brep + col0 + warp_n * 64 + ni * 16,
                                   D_CAT, wmma::mem_row_major);

    load_chunk(0, 0);

    for (int ch = 0; ch < nchunks; ch++) {
        int s = ch & 1;
        CP_WAIT(0);
        __syncthreads();
        if (ch + 1 < nchunks)
            load_chunk(ch + 1, s ^ 1);   // DMA overlaps MMAs below

        const __nv_bfloat16* sAhi = (const __nv_bfloat16*)(smem + s * STAGE_B);
        const __nv_bfloat16* sBhi = (const __nv_bfloat16*)(smem + s * STAGE_B + 2 * TILE_B);

#pragma unroll
        for (int ks = 0; ks < TKC / 16; ks++) {
            wmma::fragment<wmma::matrix_a, 16, 16, 16, __nv_bfloat16, wmma::row_major> ah[2], al[2];
#pragma unroll
            for (int mi = 0; mi < 2; mi++) {
                const __nv_bfloat16* pa = sAhi + (warp_m * 32 + mi * 16) * LDA + ks * 16;
                wmma::load_matrix_sync(ah[mi], pa, LDA);
                wmma::load_matrix_sync(al[mi], pa + (TILE_B / 2), LDA);
            }
#pragma unroll
            for (int ni = 0; ni < 4; ni++) {
                wmma::fragment<wmma::matrix_b, 16, 16, 16, __nv_bfloat16, wmma::col_major> bh, bl;
                const __nv_bfloat16* pb = sBhi + (warp_n * 64 + ni * 16) * LDA + ks * 16;
                wmma::load_matrix_sync(bh, pb, LDA);
                wmma::load_matrix_sync(bl, pb + (TILE_B / 2), LDA);
#pragma unroll
                for (int mi = 0; mi < 2; mi++) {
                    wmma::mma_sync(acc[mi][ni], ah[mi], bh, acc[mi][ni]);
                    wmma::mma_sync(acc[mi][ni], ah[mi], bl, acc[mi][ni]);
                    wmma::mma_sync(acc[mi][ni], al[mi], bh, acc[mi][ni]);
                }
            }
        }
    }
    __syncthreads();

    // ---- sectioned epilogue ----
    int sec = blockIdx.x;
    float* warpbuf = (float*)(smem) + wid * 256;   // 1KB per warp
    int lane = tid & 31;

    if (sec == 0 || sec == 3) {
        float* dst = (sec == 0) ? Oq : Os;   // fp32 compact [N,128]
#pragma unroll
        for (int mi = 0; mi < 2; mi++) {
            int rbase = row0 + warp_m * 32 + mi * 16;
            bool full = (rbase + 16 <= M);
#pragma unroll
            for (int ni = 0; ni < 4; ni++) {
                int cl = warp_n * 64 + ni * 16;   // 0..127 within section
                if (full) {
                    wmma::store_matrix_sync(dst + (size_t)rbase * 128 + cl, acc[mi][ni],
                                            128, wmma::mem_row_major);
                } else {
                    wmma::store_matrix_sync(warpbuf, acc[mi][ni], 16, wmma::mem_row_major);
                    __syncwarp();
                    int r = lane >> 1;
                    int c8 = (lane & 1) * 8;
                    int gr = rbase + r;
                    if (gr < M) {
                        float4 v0 = *(float4*)(warpbuf + r * 16 + c8);
                        float4 v1 = *(float4*)(warpbuf + r * 16 + c8 + 4);
                        *(float4*)(dst + (size_t)gr * 128 + cl + c8) = v0;
                        *(float4*)(dst + (size_t)gr * 128 + cl + c8 + 4) = v1;
                    }
                    __syncwarp();
                }
            }
        }
    } else {
        __nv_bfloat16* dst = (sec == 1) ? Ok : Ov;   // bf16 compact [N,128]
#pragma unroll
        for (int mi = 0; mi < 2; mi++) {
            int rbase = row0 + warp_m * 32 + mi * 16;
#pragma unroll
            for (int ni = 0; ni < 4; ni++) {
                int cl = warp_n * 64 + ni * 16;
                wmma::store_matrix_sync(warpbuf, acc[mi][ni], 16, wmma::mem_row_major);
                __syncwarp();
                int r = lane >> 1;
                int c8 = (lane & 1) * 8;
                int gr = rbase + r;
                if (gr < M) {
                    float4 v0 = *(float4*)(warpbuf + r * 16 + c8);
                    float4 v1 = *(float4*)(warpbuf + r * 16 + c8 + 4);
                    __nv_bfloat162 b0 = __float22bfloat162_rn(make_float2(v0.x, v0.y));
                    __nv_bfloat162 b1 = __float22bfloat162_rn(make_float2(v0.z, v0.w));
                    __nv_bfloat162 b2 = __float22bfloat162_rn(make_float2(v1.x, v1.y));
                    __nv_bfloat162 b3 = __float22bfloat162_rn(make_float2(v1.z, v1.w));
                    uint4 pk;
                    pk.x = *(uint32_t*)&b0; pk.y = *(uint32_t*)&b1;
                    pk.z = *(uint32_t*)&b2; pk.w = *(uint32_t*)&b3;
                    *(uint4*)(dst + (size_t)gr * 128 + cl + c8) = pk;
                }
                __syncwarp();
            }
        }
    }
}

// ================= fused attention: compact q/k/v/skip arrays ================
// k,v bf16 [N,128] (25.6MB, L2-resident); q,skip fp32 [N,128].
__global__ void __launch_bounds__(256) attn_kernel(
    const float* __restrict__ qs, const __nv_bfloat16* __restrict__ kb,
    const __nv_bfloat16* __restrict__ vb, const float* __restrict__ sk,
    const int* __restrict__ off, const int* __restrict__ csr_src,
    float* __restrict__ out_f32, __nv_bfloat16* __restrict__ out_hi,
    __nv_bfloat16* __restrict__ out_lo, int mode) {
    int warp = (blockIdx.x * blockDim.x + threadIdx.x) >> 5;
    int lane = threadIdx.x & 31;
    if (warp >= N_NODES) return;
    const float scale = 0.0883883476483184f;   // 1/sqrt(128)

    float4 q = *(const float4*)(qs + (size_t)warp * 128 + lane * 4);
    int e0 = off[warp], e1 = off[warp + 1];

    float ax = 0.f, ay = 0.f, az = 0.f, aw = 0.f, den = 0.f;
    int e = e0;
    for (; e + 2 <= e1; e += 2) {
        int s0 = csr_src[e];
        int s1 = csr_src[e + 1];
        uint2 kw0 = *(const uint2*)(kb + (size_t)s0 * 128 + lane * 4);
        uint2 kw1 = *(const uint2*)(kb + (size_t)s1 * 128 + lane * 4);
        uint2 vw0 = *(const uint2*)(vb + (size_t)s0 * 128 + lane * 4);
        uint2 vw1 = *(const uint2*)(vb + (size_t)s1 * 128 + lane * 4);
        float2 k0a = __bfloat1622float2(*(__nv_bfloat162*)&kw0.x);
        float2 k0b = __bfloat1622float2(*(__nv_bfloat162*)&kw0.y);
        float2 k1a = __bfloat1622float2(*(__nv_bfloat162*)&kw1.x);
        float2 k1b = __bfloat1622float2(*(__nv_bfloat162*)&kw1.y);
        float p0 = q.x * k0a.x + q.y * k0a.y + q.z * k0b.x + q.w * k0b.y;
        float p1 = q.x * k1a.x + q.y * k1a.y + q.z * k1b.x + q.w * k1b.y;
        p0 += __shfl_xor_sync(0xFFFFFFFFu, p0, 16);
        p1 += __shfl_xor_sync(0xFFFFFFFFu, p1, 16);
        p0 += __shfl_xor_sync(0xFFFFFFFFu, p0, 8);
        p1 += __shfl_xor_sync(0xFFFFFFFFu, p1, 8);
        p0 += __shfl_xor_sync(0xFFFFFFFFu, p0, 4);
        p1 += __shfl_xor_sync(0xFFFFFFFFu, p1, 4);
        p0 += __shfl_xor_sync(0xFFFFFFFFu, p0, 2);
        p1 += __shfl_xor_sync(0xFFFFFFFFu, p1, 2);
        p0 += __shfl_xor_sync(0xFFFFFFFFu, p0, 1);
        p1 += __shfl_xor_sync(0xFFFFFFFFu, p1, 1);
        float ex0 = __expf(p0 * scale);
        float ex1 = __expf(p1 * scale);
        float2 v0a = __bfloat1622float2(*(__nv_bfloat162*)&vw0.x);
        float2 v0b = __bfloat1622float2(*(__nv_bfloat162*)&vw0.y);
        float2 v1a = __bfloat1622float2(*(__nv_bfloat162*)&vw1.x);
        float2 v1b = __bfloat1622float2(*(__nv_bfloat162*)&vw1.y);
        ax += ex0 * v0a.x + ex1 * v1a.x;
        ay += ex0 * v0a.y + ex1 * v1a.y;
        az += ex0 * v0b.x + ex1 * v1b.x;
        aw += ex0 * v0b.y + ex1 * v1b.y;
        den += ex0 + ex1;
    }
    if (e < e1) {
        int s0 = csr_src[e];
        uint2 kw0 = *(const uint2*)(kb + (size_t)s0 * 128 + lane * 4);
        uint2 vw0 = *(const uint2*)(vb + (size_t)s0 * 128 + lane * 4);
        float2 k0a = __bfloat1622float2(*(__nv_bfloat162*)&kw0.x);
        float2 k0b = __bfloat1622float2(*(__nv_bfloat162*)&kw0.y);
        float p0 = q.x * k0a.x + q.y * k0a.y + q.z * k0b.x + q.w * k0b.y;
        p0 += __shfl_xor_sync(0xFFFFFFFFu, p0, 16);
        p0 += __shfl_xor_sync(0xFFFFFFFFu, p0, 8);
        p0 += __shfl_xor_sync(0xFFFFFFFFu, p0, 4);
        p0 += __shfl_xor_sync(0xFFFFFFFFu, p0, 2);
        p0 += __shfl_xor_sync(0xFFFFFFFFu, p0, 1);
        float ex0 = __expf(p0 * scale);
        float2 v0a = __bfloat1622float2(*(__nv_bfloat162*)&vw0.x);
        float2 v0b = __bfloat1622float2(*(__nv_bfloat162*)&vw0.y);
        ax += ex0 * v0a.x; ay += ex0 * v0a.y; az += ex0 * v0b.x; aw += ex0 * v0b.y;
        den += ex0;
    }
    float inv = (e1 > e0) ? 1.0f / den : 0.0f;
    float4 skv = *(const float4*)(sk + (size_t)warp * 128 + lane * 4);
    float4 r;
    r.x = ax * inv + skv.x;
    r.y = ay * inv + skv.y;
    r.z = az * inv + skv.z;
    r.w = aw * inv + skv.w;
    if (mode == 1) {
        r.x = fmaxf(r.x, 0.f); r.y = fmaxf(r.y, 0.f);
        r.z = fmaxf(r.z, 0.f); r.w = fmaxf(r.w, 0.f);
        __nv_bfloat162 h0 = __float22bfloat162_rn(make_float2(r.x, r.y));
        __nv_bfloat162 h1 = __float22bfloat162_rn(make_float2(r.z, r.w));
        float2 hr0 = __bfloat1622float2(h0), hr1 = __bfloat1622float2(h1);
        __nv_bfloat162 l0 = __float22bfloat162_rn(make_float2(r.x - hr0.x, r.y - hr0.y));
        __nv_bfloat162 l1 = __float22bfloat162_rn(make_float2(r.z - hr1.x, r.w - hr1.y));
        size_t base = (size_t)warp * 128 + lane * 4;
        *(__nv_bfloat162*)(out_hi + base)     = h0;
        *(__nv_bfloat162*)(out_hi + base + 2) = h1;
        *(__nv_bfloat162*)(out_lo + base)     = l0;
        *(__nv_bfloat162*)(out_lo + base + 2) = l1;
    } else {
        *(float4*)(out_f32 + (size_t)warp * 128 + lane * 4) = r;
    }
}

// ================= edge scorer: (h[a]*h[b]) @ Wl + bl =================
__global__ void __launch_bounds__(256) score_kernel(
    const float* __restrict__ h, const int* __restrict__ pos,
    const int* __restrict__ neg, const float* __restrict__ Wl,
    const float* __restrict__ bl, float* __restrict__ out) {
    int warp = (blockIdx.x * blockDim.x + threadIdx.x) >> 5;
    int lane = threadIdx.x & 31;
    if (warp >= 2 * N_PRED) return;
    int a, b;
    if (warp < N_PRED) { a = pos[warp]; b = pos[N_PRED + warp]; }
    else { int i = warp - N_PRED; a = neg[i]; b = neg[N_PRED + i]; }
    float4 ha = *(const float4*)(h + (size_t)a * 128 + lane * 4);
    float4 hb = *(const float4*)(h + (size_t)b * 128 + lane * 4);
    float4 w  = *(const float4*)(Wl + lane * 4);
    float p = ha.x * hb.x * w.x + ha.y * hb.y * w.y + ha.z * hb.z * w.z + ha.w * hb.w * w.w;
    p += __shfl_xor_sync(0xFFFFFFFFu, p, 16);
    p += __shfl_xor_sync(0xFFFFFFFFu, p, 8);
    p += __shfl_xor_sync(0xFFFFFFFFu, p, 4);
    p += __shfl_xor_sync(0xFFFFFFFFu, p, 2);
    p += __shfl_xor_sync(0xFFFFFFFFu, p, 1);
    if (lane == 0) out[warp] = p + bl[0];
}

// ================= launch =================
extern "C" void kernel_launch(void* const* d_in, const int* in_sizes, int n_in,
                              void* d_out, int out_size) {
    const float* x   = (const float*)d_in[0];
    const int*   ei  = (const int*)d_in[1];    // int32 (JAX x64 disabled)
    const int*   pos = (const int*)d_in[2];
    const int*   neg = (const int*)d_in[3];
    const float *Wq1 = (const float*)d_in[4],  *bq1 = (const float*)d_in[5];
    const float *Wk1 = (const float*)d_in[6],  *bk1 = (const float*)d_in[7];
    const float *Wv1 = (const float*)d_in[8],  *bv1 = (const float*)d_in[9];
    const float *Ws1 = (const float*)d_in[10], *bs1 = (const float*)d_in[11];
    const float *Wq2 = (const float*)d_in[12], *bq2 = (const float*)d_in[13];
    const float *Wk2 = (const float*)d_in[14], *bk2 = (const float*)d_in[15];
    const float *Wv2 = (const float*)d_in[16], *bv2 = (const float*)d_in[17];
    const float *Ws2 = (const float*)d_in[18], *bs2 = (const float*)d_in[19];
    const float *Wl  = (const float*)d_in[20], *bl  = (const float*)d_in[21];
    float* out = (float*)d_out;

    void *p;
    cudaGetSymbolAddress(&p, g_qs);    float* qs = (float*)p;
    cudaGetSymbolAddress(&p, g_sk);    float* sk = (float*)p;
    cudaGetSymbolAddress(&p, g_kb);    __nv_bfloat16* kb = (__nv_bfloat16*)p;
    cudaGetSymbolAddress(&p, g_vb);    __nv_bfloat16* vb = (__nv_bfloat16*)p;
    cudaGetSymbolAddress(&p, g_h2);    float* h2   = (float*)p;
    cudaGetSymbolAddress(&p, g_xhi);   __nv_bfloat16* xhi = (__nv_bfloat16*)p;
    cudaGetSymbolAddress(&p, g_xlo);   __nv_bfloat16* xlo = (__nv_bfloat16*)p;
    cudaGetSymbolAddress(&p, g_hhi);   __nv_bfloat16* hhi = (__nv_bfloat16*)p;
    cudaGetSymbolAddress(&p, g_hlo);   __nv_bfloat16* hlo = (__nv_bfloat16*)p;
    cudaGetSymbolAddress(&p, g_Wt1h);  __nv_bfloat16* Wt1h = (__nv_bfloat16*)p;
    cudaGetSymbolAddress(&p, g_Wt1l);  __nv_bfloat16* Wt1l = (__nv_bfloat16*)p;
    cudaGetSymbolAddress(&p, g_Wt2h);  __nv_bfloat16* Wt2h = (__nv_bfloat16*)p;
    cudaGetSymbolAddress(&p, g_Wt2l);  __nv_bfloat16* Wt2l = (__nv_bfloat16*)p;
    cudaGetSymbolAddress(&p, g_brep1); float* brep1 = (float*)p;
    cudaGetSymbolAddress(&p, g_brep2); float* brep2 = (float*)p;
    cudaGetSymbolAddress(&p, g_cnt);   int* cnt = (int*)p;
    cudaGetSymbolAddress(&p, g_off);   int* off = (int*)p;
    cudaGetSymbolAddress(&p, g_cur);   int* cur = (int*)p;
    cudaGetSymbolAddress(&p, g_csr_src); int* csr = (int*)p;

    cudaFuncSetAttribute(gemm_tc_kernel, cudaFuncAttributeMaxDynamicSharedMemorySize, GEMM_SMEM);

    dim3 ggrid(D_CAT / TN, (N_NODES + TM - 1) / TM);

    // prep (launches 0-2)
    split_kernel<<<(N_NODES * D_IN + 255) / 256, 256>>>(x, xhi, xlo, N_NODES * D_IN);
    packW_kernel<<<(D_CAT * D_IN + 255) / 256, 256>>>(Wq1, Wk1, Wv1, Ws1, bq1, bk1, bv1, bs1,
                                                      Wt1h, Wt1l, brep1, D_IN);
    packW_kernel<<<(D_CAT * 128 + 255) / 256, 256>>>(Wq2, Wk2, Wv2, Ws2, bq2, bk2, bv2, bs2,
                                                     Wt2h, Wt2l, brep2, 128);

    // GEMM layer 1 (launch index 3 — the one ncu profiles)
    gemm_tc_kernel<<<ggrid, 256, GEMM_SMEM>>>(xhi, xlo, Wt1h, Wt1l, brep1,
                                              qs, kb, vb, sk, N_NODES, D_IN);

    // CSR by dst
    zero_cnt_kernel<<<(N_NODES + 255) / 256, 256>>>(cnt);
    count_kernel<<<(N_EDGES + 255) / 256, 256>>>(ei, cnt);
    scan_kernel<<<1, 1024>>>(cnt, off, cur);
    scatter_kernel<<<(N_EDGES + 255) / 256, 256>>>(ei, cur, csr);

    // layer 1 attention
    attn_kernel<<<(N_NODES * 32 + 255) / 256, 256>>>(qs, kb, vb, sk, off, csr,
                                                     nullptr, hhi, hlo, 1);

    // layer 2
    gemm_tc_kernel<<<ggrid, 256, GEMM_SMEM>>>(hhi, hlo, Wt2h, Wt2l, brep2,
                                              qs, kb, vb, sk, N_NODES, 128);
    attn_kernel<<<(N_NODES * 32 + 255) / 256, 256>>>(qs, kb, vb, sk, off, csr,
                                                     h2, nullptr, nullptr, 0);

    // scorer
    score_kernel<<<(2 * N_PRED * 32 + 255) / 256, 256>>>(h2, pos, neg, Wl, bl, out);
}